// round 2
// baseline (speedup 1.0000x reference)
#include <cuda_runtime.h>
#include <cuda_bf16.h>
#include <cstdint>

// Problem constants
#define Bq   4
#define Nq   256
#define HIDq 256
#define Eq   64
#define Hq   4
#define Dq   32
#define OUTq 128      // HID/2
#define AGGq 260      // H*(2D+1)
#define ROWS (Bq*Nq)  // 1024

// Scratch (static device allocations are allowed)
__device__ float g_qk[ROWS * Hq * Eq];     // [row][h*64+e]
__device__ float g_multi[ROWS * AGGq];     // [row][h*65+k]

// ---------------- f32x2 helpers (Blackwell packed fp32) ----------------
__device__ __forceinline__ unsigned long long pack2(float a, float b) {
    unsigned long long r;
    asm("mov.b64 %0, {%1, %2};" : "=l"(r) : "f"(a), "f"(b));
    return r;
}
__device__ __forceinline__ void unpack2(unsigned long long v, float& a, float& b) {
    asm("mov.b64 {%0, %1}, %2;" : "=f"(a), "=f"(b) : "l"(v));
}
__device__ __forceinline__ unsigned long long fma2(unsigned long long a,
                                                   unsigned long long b,
                                                   unsigned long long c) {
    unsigned long long d;
    asm("fma.rn.f32x2 %0, %1, %2, %3;" : "=l"(d) : "l"(a), "l"(b), "l"(c));
    return d;
}
__device__ __forceinline__ unsigned long long add2(unsigned long long a,
                                                   unsigned long long b) {
    unsigned long long d;
    asm("add.rn.f32x2 %0, %1, %2;" : "=l"(d) : "l"(a), "l"(b));
    return d;
}
__device__ __forceinline__ unsigned long long mul2(unsigned long long a,
                                                   unsigned long long b) {
    unsigned long long d;
    asm("mul.rn.f32x2 %0, %1, %2;" : "=l"(d) : "l"(a), "l"(b));
    return d;
}

// =======================================================================
// Kernel 1: qk[row][h][e] = sum_d (h_x[row]·W_Q[h*32+d]) * W_K[h*32+d][e]
// grid 128 blocks x 256 threads; each block does 8 rows.
// =======================================================================
__global__ __launch_bounds__(256)
void qk_kernel(const float* __restrict__ hx,
               const float* __restrict__ WQ,
               const float* __restrict__ WK) {
    __shared__ float s_hx[8][256];
    __shared__ float s_w[128][65];
    __shared__ float s_q[8][128];

    const int tid  = threadIdx.x;
    const int row0 = blockIdx.x * 8;

    // load 8 h_x rows (coalesced)
    for (int i = tid; i < 8 * 256; i += 256)
        s_hx[i >> 8][i & 255] = hx[row0 * 256 + i];
    __syncthreads();

    // q = h_x @ W_Q^T  (chunked over x)
    const int c  = tid & 127;
    const int rh = tid >> 7;
    float acc[4] = {0.f, 0.f, 0.f, 0.f};
    for (int ch = 0; ch < 4; ch++) {
        for (int i = tid; i < 128 * 64; i += 256) {
            int cc = i >> 6, j = i & 63;
            s_w[cc][j] = WQ[cc * 256 + ch * 64 + j];
        }
        __syncthreads();
        #pragma unroll 8
        for (int j = 0; j < 64; j++) {
            float w = s_w[c][j];
            #pragma unroll
            for (int k = 0; k < 4; k++)
                acc[k] += s_hx[rh * 4 + k][ch * 64 + j] * w;
        }
        __syncthreads();
    }
    #pragma unroll
    for (int k = 0; k < 4; k++) s_q[rh * 4 + k][c] = acc[k];
    __syncthreads();

    // load W_K [128][64]
    for (int i = tid; i < 128 * 64; i += 256)
        s_w[i >> 6][i & 63] = WK[i];
    __syncthreads();

    // qk: thread (h = tid/64, e = tid%64), all 8 rows
    const int h = tid >> 6;
    const int e = tid & 63;
    #pragma unroll
    for (int r = 0; r < 8; r++) {
        float s = 0.f;
        #pragma unroll 8
        for (int d = 0; d < 32; d++)
            s += s_q[r][h * 32 + d] * s_w[h * 32 + d][e];
        g_qk[(row0 + r) * 256 + h * 64 + e] = s;
    }
}

// =======================================================================
// Kernel 2 (main): per (b,n) row
//   - scores over m + softmax over H  (streaming, no m-reduction needed)
//   - fused V projection + attn*v sum + attn*v max (f32x2 packed)
// grid 1024 x 256 threads, dynamic smem.
// SMEM layout (floats):
//   s_hep [128 m-pairs][132]  : hep[m2][2e+comp] = h_e[m][e], rows padded
//   s_qk  [256]
//   s_attn[4*256]             : attn[h*256 + m]  (pairs are ull-aligned)
//   s_asum[4]
// =======================================================================
#define HEPS 132
#define SMEM_MAIN ((128 * HEPS + 256 + 1024 + 4) * 4)

__global__ __launch_bounds__(256, 2)
void main_kernel(const float* __restrict__ h_e,
                 const float* __restrict__ h_m,
                 const float* __restrict__ W_V) {
    extern __shared__ float sm[];
    float* s_hep  = sm;
    float* s_qk   = sm + 128 * HEPS;
    float* s_attn = s_qk + 256;
    float* s_asum = s_attn + 1024;

    const int bn  = blockIdx.x;
    const int tid = threadIdx.x;

    // ---- load phase ----
    const float4* src4 = (const float4*)(h_e + (size_t)bn * (Nq * Eq));
    #pragma unroll
    for (int it = 0; it < 16; it++) {
        int flat = tid + it * 256;          // float4 index, 0..4095
        int m  = flat >> 4;
        int e4 = (flat & 15) << 2;
        float4 v = src4[flat];
        float* dst = s_hep + (m >> 1) * HEPS + (m & 1);
        dst[(e4 + 0) * 2] = v.x;
        dst[(e4 + 1) * 2] = v.y;
        dst[(e4 + 2) * 2] = v.z;
        dst[(e4 + 3) * 2] = v.w;
    }
    s_qk[tid] = g_qk[bn * 256 + tid];
    if (tid < 4) s_asum[tid] = 0.f;
    const float maskv = h_m[bn];
    __syncthreads();

    // ---- scores + softmax over heads (thread = m) ----
    {
        const int m = tid;
        const float* hb = s_hep + (m >> 1) * HEPS + (m & 1);
        float s0 = 0.f, s1 = 0.f, s2 = 0.f, s3 = 0.f;
        #pragma unroll 8
        for (int e = 0; e < 64; e++) {
            float he = hb[e * 2];
            s0 += he * s_qk[e];
            s1 += he * s_qk[64 + e];
            s2 += he * s_qk[128 + e];
            s3 += he * s_qk[192 + e];
        }
        const float scal = 0.1767766952966369f;  // 1/sqrt(32)
        s0 *= scal; s1 *= scal; s2 *= scal; s3 *= scal;
        if (maskv == 0.f) {
            const float ninf = __int_as_float(0xff800000);
            s0 = s1 = s2 = s3 = ninf;
        }
        float mx = fmaxf(fmaxf(s0, s1), fmaxf(s2, s3));
        float e0 = __expf(s0 - mx), e1 = __expf(s1 - mx);
        float e2 = __expf(s2 - mx), e3 = __expf(s3 - mx);
        float r  = 1.f / (e0 + e1 + e2 + e3);
        float a0 = e0 * r, a1 = e1 * r, a2 = e2 * r, a3 = e3 * r;
        s_attn[0 * 256 + m] = a0;
        s_attn[1 * 256 + m] = a1;
        s_attn[2 * 256 + m] = a2;
        s_attn[3 * 256 + m] = a3;
        // attn_sum warp-reduce + smem atomics
        float t0 = a0, t1 = a1, t2 = a2, t3 = a3;
        #pragma unroll
        for (int off = 16; off; off >>= 1) {
            t0 += __shfl_xor_sync(0xffffffffu, t0, off);
            t1 += __shfl_xor_sync(0xffffffffu, t1, off);
            t2 += __shfl_xor_sync(0xffffffffu, t2, off);
            t3 += __shfl_xor_sync(0xffffffffu, t3, off);
        }
        if ((tid & 31) == 0) {
            atomicAdd(&s_asum[0], t0);
            atomicAdd(&s_asum[1], t1);
            atomicAdd(&s_asum[2], t2);
            atomicAdd(&s_asum[3], t3);
        }
    }
    __syncthreads();

    // ---- V projection + attn*v sum/max (f32x2) ----
    const int c  = tid >> 1;     // output channel 0..127
    const int eh = tid & 1;      // e-half (lane pair)
    const int h  = c >> 5;

    // W_V half-row, duplicated into f32x2 regs (once)
    unsigned long long wv2[32];
    {
        const float4* wvp = (const float4*)(W_V + c * 64 + eh * 32);
        #pragma unroll
        for (int j = 0; j < 8; j++) {
            float4 w = wvp[j];
            wv2[4 * j + 0] = pack2(w.x, w.x);
            wv2[4 * j + 1] = pack2(w.y, w.y);
            wv2[4 * j + 2] = pack2(w.z, w.z);
            wv2[4 * j + 3] = pack2(w.w, w.w);
        }
    }

    unsigned long long accs = 0ull;  // (0.f, 0.f)
    const float ninf = __int_as_float(0xff800000);
    float amax0 = ninf, amax1 = ninf;
    const unsigned long long* attnp =
        (const unsigned long long*)(s_attn + h * 256);

    for (int m2 = 0; m2 < 128; m2++) {
        const ulonglong2* hp =
            (const ulonglong2*)(s_hep + m2 * HEPS + eh * 64);
        unsigned long long va = 0ull, vb = 0ull, vc = 0ull, vd = 0ull;
        #pragma unroll
        for (int j = 0; j < 16; j += 4) {
            ulonglong2 u0 = hp[j + 0];
            ulonglong2 u1 = hp[j + 1];
            ulonglong2 u2 = hp[j + 2];
            ulonglong2 u3 = hp[j + 3];
            va = fma2(u0.x, wv2[2 * j + 0], va);
            vb = fma2(u0.y, wv2[2 * j + 1], vb);
            vc = fma2(u1.x, wv2[2 * j + 2], vc);
            vd = fma2(u1.y, wv2[2 * j + 3], vd);
            va = fma2(u2.x, wv2[2 * j + 4], va);
            vb = fma2(u2.y, wv2[2 * j + 5], vb);
            vc = fma2(u3.x, wv2[2 * j + 6], vc);
            vd = fma2(u3.y, wv2[2 * j + 7], vd);
        }
        unsigned long long v = add2(add2(va, vb), add2(vc, vd));
        unsigned long long o = __shfl_xor_sync(0xffffffffu, v, 1);
        unsigned long long vf = add2(v, o);         // full 64-e dot, both m's
        unsigned long long at = attnp[m2];          // (attn[m0], attn[m1])
        unsigned long long aw = mul2(vf, at);
        accs = add2(accs, aw);
        float awlo, awhi;
        unpack2(aw, awlo, awhi);
        amax0 = fmaxf(amax0, awlo);
        amax1 = fmaxf(amax1, awhi);
    }

    if (eh == 0) {
        float slo, shi;
        unpack2(accs, slo, shi);
        float ssum = slo + shi;
        float smax = fmaxf(amax0, amax1);
        int   d    = c & 31;
        float asum = s_asum[h] + 1e-8f;
        float* mrow = g_multi + (size_t)bn * AGGq + h * 65;
        mrow[d]      = ssum / asum;   // aggr_mean
        if (d == 0) mrow[32] = asum;  // attn_sum (+1e-8, matching reference)
        mrow[33 + d] = smax;          // aggr_max
    }
}

// =======================================================================
// Kernel 3: out[row] = multi[row] @ W_R^T   ([1024,260] @ [260,128])
// grid 128 x 256 threads; 8 rows per block, W_R staged through smem.
// =======================================================================
__global__ __launch_bounds__(256)
void out_kernel(const float* __restrict__ W_R, float* __restrict__ out) {
    __shared__ float s_multi[8][260];
    __shared__ float s_wr[128][66];

    const int tid  = threadIdx.x;
    const int row0 = blockIdx.x * 8;

    for (int i = tid; i < 8 * 260; i += 256)
        s_multi[i / 260][i % 260] = g_multi[row0 * 260 + i];

    const int o  = tid & 127;
    const int rh = tid >> 7;
    float acc[4] = {0.f, 0.f, 0.f, 0.f};

    for (int ch = 0; ch < 4; ch++) {
        int a0 = ch * 65;
        __syncthreads();
        for (int i = tid; i < 128 * 65; i += 256) {
            int oo = i / 65, j = i % 65;
            s_wr[oo][j] = W_R[oo * 260 + a0 + j];
        }
        __syncthreads();
        #pragma unroll 5
        for (int j = 0; j < 65; j++) {
            float w = s_wr[o][j];
            #pragma unroll
            for (int k = 0; k < 4; k++)
                acc[k] += s_multi[rh * 4 + k][a0 + j] * w;
        }
    }
    #pragma unroll
    for (int k = 0; k < 4; k++)
        out[(size_t)(row0 + rh * 4 + k) * 128 + o] = acc[k];
}

// =======================================================================
extern "C" void kernel_launch(void* const* d_in, const int* in_sizes, int n_in,
                              void* d_out, int out_size) {
    (void)in_sizes; (void)n_in; (void)out_size;
    const float* h_x = (const float*)d_in[0];
    const float* h_e = (const float*)d_in[1];
    const float* h_m = (const float*)d_in[2];
    const float* W_Q = (const float*)d_in[3];
    const float* W_K = (const float*)d_in[4];
    const float* W_V = (const float*)d_in[5];
    const float* W_R = (const float*)d_in[6];
    float* out = (float*)d_out;

    cudaFuncSetAttribute(main_kernel,
                         cudaFuncAttributeMaxDynamicSharedMemorySize,
                         SMEM_MAIN);

    qk_kernel<<<128, 256>>>(h_x, W_Q, W_K);
    main_kernel<<<ROWS, 256, SMEM_MAIN>>>(h_e, h_m, W_V);
    out_kernel<<<128, 256>>>(W_R, out);
}

// round 4
// speedup vs baseline: 3.0264x; 3.0264x over previous
#include <cuda_runtime.h>
#include <cuda_bf16.h>
#include <cstdint>

typedef unsigned int       u32;
typedef unsigned long long u64;

#define ROWS 1024
#define AGG  260

__device__ float g_Mfold[256 * 256];   // [x][h*64+e], 1/sqrt(D) folded
__device__ float g_qk[ROWS * 256];
__device__ u32   g_WVh[4096];          // W_V hi bf16x2, [c*32 + e/2]
__device__ u32   g_WVl[4096];          // W_V lo bf16x2
__device__ float g_multi[ROWS * AGG];

// ---------------- f32x2 helpers ----------------
__device__ __forceinline__ u64 pack2(float a, float b) {
    u64 r; asm("mov.b64 %0, {%1, %2};" : "=l"(r) : "f"(a), "f"(b)); return r;
}
__device__ __forceinline__ void unpack2(u64 v, float& a, float& b) {
    asm("mov.b64 {%0, %1}, %2;" : "=f"(a), "=f"(b) : "l"(v));
}
__device__ __forceinline__ u64 fma2(u64 a, u64 b, u64 c) {
    u64 d; asm("fma.rn.f32x2 %0, %1, %2, %3;" : "=l"(d) : "l"(a), "l"(b), "l"(c));
    return d;
}

// ---------------- warp mma: m16n8k16 bf16, D/C f32, accumulate in-place ----
__device__ __forceinline__ void mma16816(float* d, const u32* a, const u32* b) {
    asm volatile(
        "mma.sync.aligned.m16n8k16.row.col.f32.bf16.bf16.f32 "
        "{%0,%1,%2,%3}, {%4,%5,%6,%7}, {%8,%9}, {%0,%1,%2,%3};"
        : "+f"(d[0]), "+f"(d[1]), "+f"(d[2]), "+f"(d[3])
        : "r"(a[0]), "r"(a[1]), "r"(a[2]), "r"(a[3]), "r"(b[0]), "r"(b[1]));
}

// rotation swizzle: row m (32 u32), logical col c -> conflict-free banks
#define BP(m, c) ((m) * 32 + (((c) + ((m) << 2)) & 31))

// =================== prep: Mfold + W_V bf16 hi/lo split ===================
__global__ __launch_bounds__(256)
void prep_kernel(const float* __restrict__ WQ, const float* __restrict__ WK,
                 const float* __restrict__ WV) {
    const int b = blockIdx.x, tid = threadIdx.x;
    if (b < 256) {
        __shared__ float wq[128];
        if (tid < 128) wq[tid] = WQ[tid * 256 + b];
        __syncthreads();
        const int h = tid >> 6, e = tid & 63;
        float acc = 0.f;
        #pragma unroll 8
        for (int d = 0; d < 32; d++)
            acc += wq[h * 32 + d] * WK[(h * 32 + d) * 64 + e];
        g_Mfold[b * 256 + tid] = acc * 0.1767766952966369f;  // 1/sqrt(32)
    } else {
        #pragma unroll
        for (int r = 0; r < 4; r++) {
            int idx = (b - 256) * 1024 + r * 256 + tid;  // < 4096
            int c = idx >> 5, e0 = (idx & 31) * 2;
            float x0 = WV[c * 64 + e0], x1 = WV[c * 64 + e0 + 1];
            __nv_bfloat16 h0 = __float2bfloat16(x0), h1 = __float2bfloat16(x1);
            __nv_bfloat16 l0 = __float2bfloat16(x0 - __bfloat162float(h0));
            __nv_bfloat16 l1 = __float2bfloat16(x1 - __bfloat162float(h1));
            __nv_bfloat162 hp = __halves2bfloat162(h0, h1);
            __nv_bfloat162 lp = __halves2bfloat162(l0, l1);
            g_WVh[idx] = *(u32*)&hp;
            g_WVl[idx] = *(u32*)&lp;
        }
    }
}

// =================== qk = h_x @ Mfold ===================
__global__ __launch_bounds__(256)
void qk_kernel(const float* __restrict__ hx) {
    __shared__ float sx[8][256];
    const int tid = threadIdx.x, r0 = blockIdx.x * 8;
    for (int i = tid; i < 2048; i += 256) sx[i >> 8][i & 255] = hx[r0 * 256 + i];
    __syncthreads();
    float a[8] = {0.f, 0.f, 0.f, 0.f, 0.f, 0.f, 0.f, 0.f};
    #pragma unroll 4
    for (int x = 0; x < 256; x++) {
        float mf = g_Mfold[x * 256 + tid];
        #pragma unroll
        for (int k = 0; k < 8; k++) a[k] += sx[k][x] * mf;
    }
    #pragma unroll
    for (int k = 0; k < 8; k++) g_qk[(r0 + k) * 256 + tid] = a[k];
}

// =================== main ===================
#define DYN_SMEM (2 * 32768)

__global__ __launch_bounds__(256, 2)
void main_kernel(const float* __restrict__ h_e, const float* __restrict__ h_m) {
    extern __shared__ u32 dynu[];
    __shared__ __align__(16) float s_qk[256];
    __shared__ float s_attn[1024];
    __shared__ float s_asum[4];
    __shared__ float s_ps[2][128];
    __shared__ float s_pm[2][128];

    u32* s_bhi = dynu;           // [256 rows m][32 u32], rotation-swizzled
    u32* s_blo = dynu + 8192;

    const int bn   = blockIdx.x;
    const int tid  = threadIdx.x;
    const int wid  = tid >> 5;
    const int lane = tid & 31;
    const int gid  = lane >> 2;
    const int tid4 = lane & 3;
    const int cg   = wid & 3;    // c-group = head
    const int mh   = wid >> 2;   // m-half
    const int cbase = cg * 32;

    if (tid < 4) s_asum[tid] = 0.f;

    // ---- convert h_e -> bf16 hi/lo swizzled smem ----
    const float4* src = (const float4*)(h_e + (size_t)bn * 16384);
    #pragma unroll
    for (int it = 0; it < 16; it++) {
        int flat = it * 256 + tid;
        int m = flat >> 4, c0 = (flat & 15) * 2;
        float4 v = src[flat];
        __nv_bfloat16 b0 = __float2bfloat16(v.x), b1 = __float2bfloat16(v.y);
        __nv_bfloat16 b2 = __float2bfloat16(v.z), b3 = __float2bfloat16(v.w);
        __nv_bfloat16 l0 = __float2bfloat16(v.x - __bfloat162float(b0));
        __nv_bfloat16 l1 = __float2bfloat16(v.y - __bfloat162float(b1));
        __nv_bfloat16 l2 = __float2bfloat16(v.z - __bfloat162float(b2));
        __nv_bfloat16 l3 = __float2bfloat16(v.w - __bfloat162float(b3));
        __nv_bfloat162 h01 = __halves2bfloat162(b0, b1);
        __nv_bfloat162 h23 = __halves2bfloat162(b2, b3);
        __nv_bfloat162 q01 = __halves2bfloat162(l0, l1);
        __nv_bfloat162 q23 = __halves2bfloat162(l2, l3);
        s_bhi[BP(m, c0)]     = *(u32*)&h01;
        s_bhi[BP(m, c0 + 1)] = *(u32*)&h23;
        s_blo[BP(m, c0)]     = *(u32*)&q01;
        s_blo[BP(m, c0 + 1)] = *(u32*)&q23;
    }
    s_qk[tid] = g_qk[bn * 256 + tid];
    const float maskv = h_m[bn];

    // ---- A fragments (W_V hi/lo) -> registers, 2 c-tiles per warp ----
    u32 Ah[2][16], Al[2][16];
    #pragma unroll
    for (int j = 0; j < 2; j++) {
        int r0 = cbase + j * 16 + gid;
        #pragma unroll
        for (int ks = 0; ks < 4; ks++) {
            int b0 = r0 * 32 + ks * 8 + tid4;
            int b1 = (r0 + 8) * 32 + ks * 8 + tid4;
            Ah[j][ks * 4 + 0] = g_WVh[b0];
            Ah[j][ks * 4 + 1] = g_WVh[b1];
            Ah[j][ks * 4 + 2] = g_WVh[b0 + 4];
            Ah[j][ks * 4 + 3] = g_WVh[b1 + 4];
            Al[j][ks * 4 + 0] = g_WVl[b0];
            Al[j][ks * 4 + 1] = g_WVl[b1];
            Al[j][ks * 4 + 2] = g_WVl[b0 + 4];
            Al[j][ks * 4 + 3] = g_WVl[b1 + 4];
        }
    }
    __syncthreads();

    // ---- scores + softmax over heads (thread = m) ----
    {
        const int m = tid;
        u64 acc0 = 0ull, acc1 = 0ull, acc2 = 0ull, acc3 = 0ull;
        const u64* qp = (const u64*)s_qk;
        #pragma unroll 8
        for (int j = 0; j < 32; j++) {
            int ep = (j + m) & 31;                       // bank-spread order
            int pi = BP(m, ep);
            u32 h2 = s_bhi[pi], l2 = s_blo[pi];
            float2 fh = __bfloat1622float2(*(__nv_bfloat162*)&h2);
            float2 fl = __bfloat1622float2(*(__nv_bfloat162*)&l2);
            u64 he = pack2(fh.x + fl.x, fh.y + fl.y);
            acc0 = fma2(he, qp[ep],      acc0);
            acc1 = fma2(he, qp[32 + ep], acc1);
            acc2 = fma2(he, qp[64 + ep], acc2);
            acc3 = fma2(he, qp[96 + ep], acc3);
        }
        float x, y, s0, s1, s2, s3;
        unpack2(acc0, x, y); s0 = x + y;
        unpack2(acc1, x, y); s1 = x + y;
        unpack2(acc2, x, y); s2 = x + y;
        unpack2(acc3, x, y); s3 = x + y;
        if (maskv == 0.f) {
            const float ninf = __int_as_float(0xff800000);
            s0 = s1 = s2 = s3 = ninf;
        }
        float mx = fmaxf(fmaxf(s0, s1), fmaxf(s2, s3));
        float e0 = __expf(s0 - mx), e1 = __expf(s1 - mx);
        float e2 = __expf(s2 - mx), e3 = __expf(s3 - mx);
        float r  = 1.f / (e0 + e1 + e2 + e3);
        float a0 = e0 * r, a1 = e1 * r, a2 = e2 * r, a3 = e3 * r;
        s_attn[m]       = a0;
        s_attn[256 + m] = a1;
        s_attn[512 + m] = a2;
        s_attn[768 + m] = a3;
        float t0 = a0, t1 = a1, t2 = a2, t3 = a3;
        #pragma unroll
        for (int off = 16; off; off >>= 1) {
            t0 += __shfl_xor_sync(0xffffffffu, t0, off);
            t1 += __shfl_xor_sync(0xffffffffu, t1, off);
            t2 += __shfl_xor_sync(0xffffffffu, t2, off);
            t3 += __shfl_xor_sync(0xffffffffu, t3, off);
        }
        if (lane == 0) {
            atomicAdd(&s_asum[0], t0);
            atomicAdd(&s_asum[1], t1);
            atomicAdd(&s_asum[2], t2);
            atomicAdd(&s_asum[3], t3);
        }
    }
    __syncthreads();

    // ---- mainloop: 16 m-tiles x 2 c-tiles, 3-term bf16 mma + fused epilogue ----
    const float ninf = __int_as_float(0xff800000);
    float sum0 = 0.f, sum1 = 0.f, sum2 = 0.f, sum3 = 0.f;
    float mx0 = ninf, mx1 = ninf, mx2 = ninf, mx3 = ninf;
    const float* ap = s_attn + cg * 256;

    for (int t = 0; t < 16; t++) {
        const int mbase = mh * 128 + t * 8;
        const int mrow  = mbase + gid;
        u32 Bh[8], Bl[8];
        #pragma unroll
        for (int ks = 0; ks < 4; ks++) {
            int c0 = ks * 8 + tid4;
            Bh[ks * 2]     = s_bhi[BP(mrow, c0)];
            Bh[ks * 2 + 1] = s_bhi[BP(mrow, c0 + 4)];
            Bl[ks * 2]     = s_blo[BP(mrow, c0)];
            Bl[ks * 2 + 1] = s_blo[BP(mrow, c0 + 4)];
        }
        float2 at = *(const float2*)(ap + mbase + 2 * tid4);
        #pragma unroll
        for (int j = 0; j < 2; j++) {
            float d[4] = {0.f, 0.f, 0.f, 0.f};
            #pragma unroll
            for (int ks = 0; ks < 4; ks++) {
                mma16816(d, &Ah[j][ks * 4], &Bh[ks * 2]);
                mma16816(d, &Ah[j][ks * 4], &Bl[ks * 2]);
                mma16816(d, &Al[j][ks * 4], &Bh[ks * 2]);
            }
            float w0 = at.x * d[0], w1 = at.y * d[1];
            float w2 = at.x * d[2], w3 = at.y * d[3];
            if (j == 0) {
                sum0 += w0 + w1; sum1 += w2 + w3;
                mx0 = fmaxf(mx0, fmaxf(w0, w1));
                mx1 = fmaxf(mx1, fmaxf(w2, w3));
            } else {
                sum2 += w0 + w1; sum3 += w2 + w3;
                mx2 = fmaxf(mx2, fmaxf(w0, w1));
                mx3 = fmaxf(mx3, fmaxf(w2, w3));
            }
        }
    }

    // reduce across quad (tid4)
    #pragma unroll
    for (int off = 1; off <= 2; off <<= 1) {
        sum0 += __shfl_xor_sync(0xffffffffu, sum0, off);
        sum1 += __shfl_xor_sync(0xffffffffu, sum1, off);
        sum2 += __shfl_xor_sync(0xffffffffu, sum2, off);
        sum3 += __shfl_xor_sync(0xffffffffu, sum3, off);
        mx0 = fmaxf(mx0, __shfl_xor_sync(0xffffffffu, mx0, off));
        mx1 = fmaxf(mx1, __shfl_xor_sync(0xffffffffu, mx1, off));
        mx2 = fmaxf(mx2, __shfl_xor_sync(0xffffffffu, mx2, off));
        mx3 = fmaxf(mx3, __shfl_xor_sync(0xffffffffu, mx3, off));
    }
    if (tid4 == 0) {
        s_ps[mh][cbase + gid]      = sum0;  s_pm[mh][cbase + gid]      = mx0;
        s_ps[mh][cbase + gid + 8]  = sum1;  s_pm[mh][cbase + gid + 8]  = mx1;
        s_ps[mh][cbase + gid + 16] = sum2;  s_pm[mh][cbase + gid + 16] = mx2;
        s_ps[mh][cbase + gid + 24] = sum3;  s_pm[mh][cbase + gid + 24] = mx3;
    }
    __syncthreads();

    if (tid < 128) {
        const int c = tid, h = c >> 5, d = c & 31;
        float s  = s_ps[0][c] + s_ps[1][c];
        float mx = fmaxf(s_pm[0][c], s_pm[1][c]);
        float asum = s_asum[h] + 1e-8f;
        float* mrow = g_multi + (size_t)bn * AGG + h * 65;
        mrow[d]      = s / asum;
        if (d == 0) mrow[32] = asum;
        mrow[33 + d] = mx;
    }
}

// =================== out = multi @ W_R^T ===================
__global__ __launch_bounds__(256)
void out_kernel(const float* __restrict__ W_R, float* __restrict__ out) {
    __shared__ float s_multi[8][260];
    __shared__ float s_wr[128][66];
    const int tid = threadIdx.x, row0 = blockIdx.x * 8;
    for (int i = tid; i < 8 * 260; i += 256)
        s_multi[i / 260][i % 260] = g_multi[row0 * 260 + i];
    const int o = tid & 127, rh = tid >> 7;
    float acc[4] = {0.f, 0.f, 0.f, 0.f};
    for (int ch = 0; ch < 4; ch++) {
        int a0 = ch * 65;
        __syncthreads();
        for (int i = tid; i < 128 * 65; i += 256) {
            int oo = i / 65, j = i % 65;
            s_wr[oo][j] = W_R[oo * 260 + a0 + j];
        }
        __syncthreads();
        #pragma unroll 5
        for (int j = 0; j < 65; j++) {
            float w = s_wr[o][j];
            #pragma unroll
            for (int k = 0; k < 4; k++)
                acc[k] += s_multi[rh * 4 + k][a0 + j] * w;
        }
    }
    #pragma unroll
    for (int k = 0; k < 4; k++)
        out[(size_t)(row0 + rh * 4 + k) * 128 + o] = acc[k];
}

// =================== launch ===================
extern "C" void kernel_launch(void* const* d_in, const int* in_sizes, int n_in,
                              void* d_out, int out_size) {
    (void)in_sizes; (void)n_in; (void)out_size;
    const float* h_x = (const float*)d_in[0];
    const float* h_e = (const float*)d_in[1];
    const float* h_m = (const float*)d_in[2];
    const float* W_Q = (const float*)d_in[3];
    const float* W_K = (const float*)d_in[4];
    const float* W_V = (const float*)d_in[5];
    const float* W_R = (const float*)d_in[6];
    float* out = (float*)d_out;

    cudaFuncSetAttribute(main_kernel,
                         cudaFuncAttributeMaxDynamicSharedMemorySize, DYN_SMEM);

    prep_kernel<<<260, 256>>>(W_Q, W_K, W_V);
    qk_kernel<<<128, 256>>>(h_x);
    main_kernel<<<ROWS, 256, DYN_SMEM>>>(h_e, h_m);
    out_kernel<<<128, 256>>>(W_R, out);
}